// round 2
// baseline (speedup 1.0000x reference)
#include <cuda_runtime.h>
#include <math.h>
#include <stdint.h>

#define H 2048
#define E 64
#define TOPK 4
#define S 4096
#define SW 1024
#define NEGF (-3.4028234663852886e38f)   // float32 min
#define INV_SQRT_H 0.022097086912079608f // 1/sqrt(2048)

// scratch (device globals: allocation-free)
__device__ float g_ws[E * H];     // proj_w * scale * H^-0.5
__device__ int   g_gid[8 * S];    // vision group ids per (b, s)

// ---------------------------------------------------------------------------
// Kernel 1: fold scale & H^-0.5 into projection weights
// ---------------------------------------------------------------------------
__global__ void ws_kernel(const float* __restrict__ proj_w,
                          const float* __restrict__ scale) {
    int i = blockIdx.x * blockDim.x + threadIdx.x;
    if (i < E * H) {
        g_ws[i] = proj_w[i] * scale[i & (H - 1)] * INV_SQRT_H;
    }
}

// ---------------------------------------------------------------------------
// Kernel 2: vision group ids (block-wide prefix scan, 1 block per batch row)
// ---------------------------------------------------------------------------
__global__ __launch_bounds__(1024) void gid_kernel(const int* __restrict__ mm) {
    int b = blockIdx.x;
    const int* row = mm + (size_t)b * S;
    int t = threadIdx.x;           // 1024 threads, 4 elems each
    int base = t * 4;

    int v[4];
    bool isv[4];
#pragma unroll
    for (int j = 0; j < 4; j++) {
        v[j] = row[base + j];
        isv[j] = (v[j] == 1) || (v[j] == 2);
    }
    bool prev = false;
    if (base > 0) {
        int p = row[base - 1];
        prev = (p == 1) || (p == 2);
    }
    int pre[4];
    int st[4];
    int cnt = 0;
#pragma unroll
    for (int j = 0; j < 4; j++) {
        st[j] = (isv[j] && !prev) ? 1 : 0;
        pre[j] = cnt;
        cnt += st[j];
        prev = isv[j];
    }

    __shared__ int sd[1024];
    sd[t] = cnt;
    __syncthreads();
    for (int off = 1; off < 1024; off <<= 1) {
        int val = sd[t];
        int add = (t >= off) ? sd[t - off] : 0;
        __syncthreads();
        sd[t] = val + add;
        __syncthreads();
    }
    int excl = sd[t] - cnt;
#pragma unroll
    for (int j = 0; j < 4; j++) {
        int incl = excl + pre[j] + st[j];
        g_gid[b * S + base + j] = isv[j] ? (incl - 1) : -1;
    }
}

// ---------------------------------------------------------------------------
// Kernel 3: build full + sliding additive masks
//   block = 4 q-rows; smem holds the whole kv row of packed/gid ids
// ---------------------------------------------------------------------------
#define QT 4
__global__ __launch_bounds__(256) void mask_kernel(const int* __restrict__ packed,
                                                   float* __restrict__ fullm,
                                                   float* __restrict__ slidm) {
    __shared__ int sp[S];
    __shared__ int sg[S];

    const int nqb = S / QT;                    // 1024 blocks per batch
    int b = blockIdx.x / nqb;
    int qbase = (blockIdx.x % nqb) * QT;

    const int4* p4 = (const int4*)(packed + (size_t)b * S);
    const int4* g4 = (const int4*)(g_gid + (size_t)b * S);
    for (int i = threadIdx.x; i < S / 4; i += 256) {
        ((int4*)sp)[i] = p4[i];
        ((int4*)sg)[i] = g4[i];
    }
    __syncthreads();

#pragma unroll
    for (int qi = 0; qi < QT; qi++) {
        int q = qbase + qi;
        int pq = sp[q];
        int gq = sg[q];
        bool vq = (pq > 0);
        size_t rowoff = ((size_t)b * S + q) * (size_t)S;
        float4* fr = (float4*)(fullm + rowoff);
        float4* sr = (float4*)(slidm + rowoff);

        for (int i = threadIdx.x; i < S / 4; i += 256) {
            int kv = i * 4;
            float4 f, s;
            float* fp = (float*)&f;
            float* spv = (float*)&s;
#pragma unroll
            for (int j = 0; j < 4; j++) {
                int k = kv + j;
                int pk = sp[k];
                int gk = sg[k];
                bool same_doc = vq && (pq == pk);
                bool causal = (k <= q);
                bool fb = same_doc && causal;
                bool win = (q - k) < SW;
                bool svg = (gq >= 0) && (gq == gk);
                bool sb = (fb && win) || (svg && same_doc);
                fp[j]  = fb ? 0.0f : NEGF;
                spv[j] = sb ? 0.0f : NEGF;
            }
            fr[i] = f;
            sr[i] = s;
        }
    }
}

// ---------------------------------------------------------------------------
// Kernel 4: gate = sumsq + GEMM(64 tokens x 64 experts x 2048) + top-4
// ---------------------------------------------------------------------------
#define TM 64
#define KC 64
#define LDST 65   // padded smem row stride (2-way-max bank conflicts)

__global__ __launch_bounds__(256) void gate_kernel(const float* __restrict__ x,
                                                   float* __restrict__ wout,
                                                   float* __restrict__ iout) {
    __shared__ float xs[TM * LDST];
    __shared__ float wsh[E * LDST];
    __shared__ float invr[TM];

    int t = threadIdx.x;
    int n0 = blockIdx.x * TM;
    int warp = t >> 5, lane = t & 31;

    // ---- per-token sum of squares (warp handles 8 tokens) ----
#pragma unroll
    for (int i = 0; i < TM / 8; i++) {
        int tok = warp * 8 + i;
        const float4* xr = (const float4*)(x + (size_t)(n0 + tok) * H);
        float ssum = 0.f;
        for (int j = lane; j < H / 4; j += 32) {
            float4 v = xr[j];
            ssum += v.x * v.x + v.y * v.y + v.z * v.z + v.w * v.w;
        }
#pragma unroll
        for (int off = 16; off > 0; off >>= 1)
            ssum += __shfl_xor_sync(0xffffffffu, ssum, off);
        if (lane == 0) invr[tok] = rsqrtf(ssum * (1.0f / H) + 1e-6f);
    }

    // ---- GEMM mainloop: acc[4][4] per thread, 16x16 thread grid ----
    float acc[4][4];
#pragma unroll
    for (int i = 0; i < 4; i++)
#pragma unroll
        for (int j = 0; j < 4; j++) acc[i][j] = 0.f;

    int tx = t & 15, ty = t >> 4;

    for (int k0 = 0; k0 < H; k0 += KC) {
        __syncthreads();
#pragma unroll
        for (int r = 0; r < 4; r++) {
            int i = t + 256 * r;
            int row = i >> 4;            // 16 float4 per row
            int c4 = (i & 15) * 4;
            float4 v = *(const float4*)(x + (size_t)(n0 + row) * H + k0 + c4);
            float* d = &xs[row * LDST + c4];
            d[0] = v.x; d[1] = v.y; d[2] = v.z; d[3] = v.w;
            float4 w = *(const float4*)(g_ws + row * H + k0 + c4);
            float* dw = &wsh[row * LDST + c4];
            dw[0] = w.x; dw[1] = w.y; dw[2] = w.z; dw[3] = w.w;
        }
        __syncthreads();

#pragma unroll
        for (int k = 0; k < KC; k++) {
            float a[4], bvec[4];
#pragma unroll
            for (int i = 0; i < 4; i++) a[i] = xs[(ty * 4 + i) * LDST + k];
#pragma unroll
            for (int i = 0; i < 4; i++) bvec[i] = wsh[(tx * 4 + i) * LDST + k];
#pragma unroll
            for (int i = 0; i < 4; i++)
#pragma unroll
                for (int j = 0; j < 4; j++) acc[i][j] += a[i] * bvec[j];
        }
    }

    __syncthreads();
    // logits -> xs[tok * LDST + e], scaled by per-token invrms
#pragma unroll
    for (int i = 0; i < 4; i++) {
        float iv = invr[ty * 4 + i];
#pragma unroll
        for (int j = 0; j < 4; j++)
            xs[(ty * 4 + i) * LDST + (tx * 4 + j)] = acc[i][j] * iv;
    }
    __syncthreads();

    // ---- top-4 per token (warp handles 8 tokens; 2 experts per lane) ----
#pragma unroll
    for (int i = 0; i < TM / 8; i++) {
        int tok = warp * 8 + i;
        float l0 = xs[tok * LDST + lane];
        float l1 = xs[tok * LDST + lane + 32];
        float m = fmaxf(l0, l1);
#pragma unroll
        for (int off = 16; off > 0; off >>= 1)
            m = fmaxf(m, __shfl_xor_sync(0xffffffffu, m, off));
        float e0 = __expf(l0 - m);
        float e1 = __expf(l1 - m);

        float wv[TOPK];
        int widx[TOPK];
        float wsum = 0.f;
#pragma unroll
        for (int r = 0; r < TOPK; r++) {
            float v; int idx;
            if (e0 >= e1) { v = e0; idx = lane; }
            else          { v = e1; idx = lane + 32; }
#pragma unroll
            for (int off = 16; off > 0; off >>= 1) {
                float ov = __shfl_xor_sync(0xffffffffu, v, off);
                int oi = __shfl_xor_sync(0xffffffffu, idx, off);
                if (ov > v || (ov == v && oi < idx)) { v = ov; idx = oi; }
            }
            wv[r] = v; widx[r] = idx; wsum += v;
            if (idx == lane)      e0 = -1.f;
            if (idx == lane + 32) e1 = -1.f;
        }
        if (lane == 0) {
            float inv = 1.f / fmaxf(wsum, 1e-20f);
            int o = (n0 + tok) * TOPK;
#pragma unroll
            for (int r = 0; r < TOPK; r++) {
                wout[o + r] = wv[r] * inv;
                iout[o + r] = (float)widx[r];
            }
        }
    }
}

// ---------------------------------------------------------------------------
extern "C" void kernel_launch(void* const* d_in, const int* in_sizes, int n_in,
                              void* d_out, int out_size) {
    const float* x      = (const float*)d_in[0];
    const int*   packed = (const int*)d_in[1];
    const int*   mm     = (const int*)d_in[2];
    const float* scale  = (const float*)d_in[3];
    const float* proj_w = (const float*)d_in[4];

    int Ntok = in_sizes[1];           // B*S
    int B = Ntok / S;

    float* out = (float*)d_out;
    size_t mask_elems = (size_t)B * S * S;
    float* fullm = out;
    float* slidm = out + mask_elems;
    float* wout  = out + 2 * mask_elems;
    float* iout  = wout + (size_t)Ntok * TOPK;

    ws_kernel<<<(E * H + 255) / 256, 256>>>(proj_w, scale);
    gid_kernel<<<B, 1024>>>(mm);
    mask_kernel<<<B * (S / QT), 256>>>(packed, fullm, slidm);
    gate_kernel<<<Ntok / TM, 256>>>(x, wout, iout);
}